// round 16
// baseline (speedup 1.0000x reference)
#include <cuda_runtime.h>
#include <cuda_bf16.h>
#include <math.h>

#define H 512
#define W 512
#define WPR 16                 // 32-bit words per row
#define GRID 128               // 4 rows per block, oe=1 (one wave, 1 block/SM)
#define MISS (1 << 20)

// Scratch (allocation-free rule: __device__ globals)
__device__ float d_blkNum[GRID];
__device__ float d_blkDen[GRID];
__device__ unsigned d_cnt;     // zero-init; atomicInc wraps -> self-resetting

// ---------------------------------------------------------------------------
// Cold path: recompute raw/surface mask words directly from float inputs.
// Only used for pixels with nearest surface distance^2 > 10 (P ~ 3e-5 / run).
// ---------------------------------------------------------------------------
__device__ __noinline__ unsigned raw_word_f(const float* __restrict__ src,
                                            int r, int w) {
    if (r < 0 || r >= H) return 0u;
    const float* p = src + r * W + w * 32;
    unsigned x = 0;
    for (int j = 0; j < 32; ++j)
        if (p[j] != 0.0f) x |= 1u << j;
    return x;
}

__device__ __noinline__ unsigned sur_word_f(const float* __restrict__ src,
                                            int r, int w) {
    if (r < 0 || r >= H || w < 0 || w >= WPR) return 0u;
    unsigned cen = raw_word_f(src, r, w);
    unsigned up  = raw_word_f(src, r - 1, w);
    unsigned dn  = raw_word_f(src, r + 1, w);
    unsigned lb  = (w > 0)  ? ((raw_word_f(src, r, w - 1) >> 31) & 1u) : 0u;
    unsigned rb  = (w < 15) ? (raw_word_f(src, r, w + 1) & 1u) : 0u;
    unsigned lm = (cen << 1) | lb;
    unsigned rm = (cen >> 1) | (rb << 31);
    return cen & ~(up & dn & lm & rm);
}

__device__ __noinline__ float search_fb(const float* __restrict__ src,
                                        int r, int w, int bit) {
    float best = 1e12f;
    for (int dr = 0; dr < H; ++dr) {
        int dr2 = dr * dr;
        if ((float)dr2 >= best) break;
        for (int sgn = 0; sgn < 2; ++sgn) {
            if (sgn == 1 && dr == 0) continue;
            int gr = sgn ? (r + dr) : (r - dr);
            if (gr < 0 || gr >= H) continue;
            unsigned lo = sur_word_f(src, gr, w - 1);
            unsigned mi = sur_word_f(src, gr, w);
            unsigned hi = sur_word_f(src, gr, w + 1);
            unsigned long long up =
                (((unsigned long long)(mi & (0xFFFFFFFFu >> (31 - bit)))) << 32) |
                (unsigned long long)lo;
            unsigned long long dn =
                (((unsigned long long)hi) << (32 - bit)) |
                (unsigned long long)(mi >> bit);
            int dl = up ? (bit + 32) - (63 - __clzll(up)) : MISS;
            int drr = dn ? (__ffsll((long long)dn) - 1)   : MISS;
            int dc = min(dl, drr);
            if (dc <= 32) {
                best = fminf(best, (float)(dr2 + dc * dc));
            } else if ((float)(dr2 + 1024) < best) {
                int dfl = MISS, dfr = MISS;
                for (int ww = w - 2; ww >= 0; --ww) {
                    unsigned x = sur_word_f(src, gr, ww);
                    if (x) { dfl = (w - ww) * 32 + bit - (31 - __clz(x)); break; }
                }
                for (int ww = w + 2; ww < WPR; ++ww) {
                    unsigned x = sur_word_f(src, gr, ww);
                    if (x) { dfr = (ww - w) * 32 - bit + (__ffs(x) - 1); break; }
                }
                int dm = min(min(dfl, dfr), dc);
                if (dm < MISS)
                    best = fminf(best, (float)(dr2 + dm * dm));
            }
        }
    }
    return sqrtf(best);
}

// ===========================================================================
// Single kernel, 128 blocks x 512 threads (1 block/SM, single wave).
// Block b handles rows 4b..4b+3. R15 base; tail trimmed:
//   - erosion on warps 4..13 (counting warps 0-3 stay clean)
//   - warps >= 4 retire right after the erosion sync
//   - reduction scoped to warps 0..3 (4 partials)
// ===========================================================================
__global__ void __launch_bounds__(512) k_all(const float* __restrict__ pred,
                                             const float* __restrict__ gt,
                                             float* __restrict__ out) {
    __shared__ unsigned sraw[2][12][WPR];   // raw rows gb-4..gb+7
    __shared__ unsigned stg[2][10][18];     // surface rows gb-3..gb+6, padded
    __shared__ float wNum[4], wDen[4];
    __shared__ bool  isLast;

    const int c = threadIdx.x;
    const int lane = c & 31;
    const int wwarp = c >> 5;               // warp id == word index
    const int gb = blockIdx.x * 4;

    // ---- batched loads: 3 batches x 4 rows x 2 features (MLP_p1 ~ 8) ----
    #pragma unroll
    for (int bb = 0; bb < 3; ++bb) {
        float pv[4], gv[4];
        #pragma unroll
        for (int k = 0; k < 4; ++k) {
            int rr = bb * 4 + k;
            int gr = gb - 4 + rr;
            bool ok = (gr >= 0) && (gr < H);
            pv[k] = ok ? pred[gr * W + c] : 0.0f;
            gv[k] = ok ? gt[gr * W + c]   : 0.0f;
        }
        #pragma unroll
        for (int k = 0; k < 4; ++k) {
            int rr = bb * 4 + k;
            unsigned ba = __ballot_sync(0xFFFFFFFFu, pv[k] != 0.0f);
            unsigned bg = __ballot_sync(0xFFFFFFFFu, gv[k] != 0.0f);
            if (lane == 0) { sraw[0][rr][wwarp] = ba; sraw[1][rr][wwarp] = bg; }
        }
    }
    __syncthreads();

    // ---- bitwise erosion on warps 4..13 (threads 128..447) ----
    if (c >= 128 && c < 448) {
        int t = c - 128;                      // 0..319
        int f = t / 160, rest = t % 160;
        int rr = rest >> 4, ww = rest & 15;   // rr 0..9 -> surface row gb-3+rr
        int ri = rr + 1;                      // center raw row index
        unsigned cen = sraw[f][ri][ww];
        unsigned up = sraw[f][ri - 1][ww];
        unsigned dn = sraw[f][ri + 1][ww];
        unsigned lw = (ww > 0)  ? sraw[f][ri][ww - 1] : 0u;
        unsigned rw = (ww < 15) ? sraw[f][ri][ww + 1] : 0u;
        unsigned lm = (cen << 1) | (lw >> 31);
        unsigned rm = (cen >> 1) | (rw << 31);
        stg[f][rr][ww + 1] = cen & ~(up & dn & lm & rm);
    } else if (c >= 448 && c < 488) {
        int idx = c - 448;                    // 40 pad words -> 0
        int f = idx / 20, rest = idx % 20;
        stg[f][rest >> 1][(rest & 1) ? 17 : 0] = 0u;
    }
    __syncthreads();

    // warps 4..15 retire; remaining __syncthreads only involve warps 0..3
    if (wwarp >= 4) return;

    // ---- per-word ball-dilation counting (2 feat x 4 rows x 16 words) ----
    float num = 0.0f;
    float den = 0.0f;

    {
        const int f = c >> 6;            // dilated (source) feature
        const int local = c & 63;
        const int rloc = local >> 4;     // 0..3
        const int w = local & 15;
        const int gr = gb + rloc;

        unsigned a0c0, a0c1, a0c2, a0c3;
        unsigned a1c0 = 0, a1c1 = 0, a1c2 = 0, a1c3 = 0;
        unsigned a2c0 = 0, a2c1 = 0, a2c2 = 0;
        unsigned a3c0 = 0, a3c1 = 0;

        #pragma unroll
        for (int dr = -3; dr <= 3; ++dr) {
            const unsigned* row = &stg[f][rloc + 3 + dr][0];
            unsigned lo = row[w], mi = row[w + 1], hi = row[w + 2];
            unsigned c0 = mi;
            unsigned c1 = __funnelshift_r(mi, hi, 1) | __funnelshift_l(lo, mi, 1);
            const int adr = (dr < 0) ? -dr : dr;
            if (adr == 0) {
                a0c0 = c0; a0c1 = c1;
                a0c2 = __funnelshift_r(mi, hi, 2) | __funnelshift_l(lo, mi, 2);
                a0c3 = __funnelshift_r(mi, hi, 3) | __funnelshift_l(lo, mi, 3);
            } else if (adr == 1) {
                a1c0 |= c0; a1c1 |= c1;
                a1c2 |= __funnelshift_r(mi, hi, 2) | __funnelshift_l(lo, mi, 2);
                a1c3 |= __funnelshift_r(mi, hi, 3) | __funnelshift_l(lo, mi, 3);
            } else if (adr == 2) {
                a2c0 |= c0; a2c1 |= c1;
                a2c2 |= __funnelshift_r(mi, hi, 2) | __funnelshift_l(lo, mi, 2);
            } else {
                a3c0 |= c0; a3c1 |= c1;
            }
        }

        const unsigned tgt = stg[f ^ 1][rloc + 3][w + 1];
        den = (float)__popc(tgt);

        // incremental ball dilations: d^2 = 0,1,2,4,5,8,9,10
        unsigned D = a0c0, Dn;
        Dn = D | a0c1 | a1c0; num += 1.0f        * (float)__popc(tgt & Dn & ~D); D = Dn;
        Dn = D | a1c1;        num += 1.41421356f * (float)__popc(tgt & Dn & ~D); D = Dn;
        Dn = D | a0c2 | a2c0; num += 2.0f        * (float)__popc(tgt & Dn & ~D); D = Dn;
        Dn = D | a1c2 | a2c1; num += 2.23606798f * (float)__popc(tgt & Dn & ~D); D = Dn;
        Dn = D | a2c2;        num += 2.82842712f * (float)__popc(tgt & Dn & ~D); D = Dn;
        Dn = D | a0c3 | a3c0; num += 3.0f        * (float)__popc(tgt & Dn & ~D); D = Dn;
        Dn = D | a1c3 | a3c1; num += 3.16227766f * (float)__popc(tgt & Dn & ~D); D = Dn;

        // cold exact fallback (recomputes masks straight from float inputs)
        unsigned rem = tgt & ~D;
        while (rem) {
            int bt = __ffs(rem) - 1;
            rem &= rem - 1u;
            num += search_fb(f ? gt : pred, gr, w, bt);
        }
    }

    // ---- reduction among warps 0..3 only ----
    #pragma unroll
    for (int off = 16; off > 0; off >>= 1) {
        num += __shfl_down_sync(0xFFFFFFFFu, num, off);
        den += __shfl_down_sync(0xFFFFFFFFu, den, off);
    }
    if (lane == 0) { wNum[wwarp] = num; wDen[wwarp] = den; }
    __syncthreads();

    if (wwarp == 0) {
        float n = (lane < 4) ? wNum[lane] : 0.0f;
        float d = (lane < 4) ? wDen[lane] : 0.0f;
        #pragma unroll
        for (int off = 2; off > 0; off >>= 1) {
            n += __shfl_down_sync(0xFFFFFFFFu, n, off);
            d += __shfl_down_sync(0xFFFFFFFFu, d, off);
        }
        if (lane == 0) {
            d_blkNum[blockIdx.x] = n;
            d_blkDen[blockIdx.x] = d;
            __threadfence();
            unsigned old = atomicInc(&d_cnt, GRID - 1);  // wraps -> self-reset
            isLast = (old == GRID - 1);
        }
    }
    __syncthreads();

    // ---- last-block fold (warps 0..3 hold 128 partials) ----
    if (isLast) {
        float n = d_blkNum[c];
        float d = d_blkDen[c];
        #pragma unroll
        for (int off = 16; off > 0; off >>= 1) {
            n += __shfl_down_sync(0xFFFFFFFFu, n, off);
            d += __shfl_down_sync(0xFFFFFFFFu, d, off);
        }
        if (lane == 0) { wNum[wwarp] = n; wDen[wwarp] = d; }
        __syncthreads();
        if (wwarp == 0) {
            float nn = (lane < 4) ? wNum[lane] : 0.0f;
            float dd = (lane < 4) ? wDen[lane] : 0.0f;
            #pragma unroll
            for (int off = 2; off > 0; off >>= 1) {
                nn += __shfl_down_sync(0xFFFFFFFFu, nn, off);
                dd += __shfl_down_sync(0xFFFFFFFFu, dd, off);
            }
            if (lane == 0) out[0] = nn / dd;
        }
    }
}

extern "C" void kernel_launch(void* const* d_in, const int* in_sizes, int n_in,
                              void* d_out, int out_size) {
    const float* pred = (const float*)d_in[0];
    const float* gt   = (const float*)d_in[1];
    float* out = (float*)d_out;

    k_all<<<GRID, 512>>>(pred, gt, out);
}

// round 17
// speedup vs baseline: 1.0811x; 1.0811x over previous
#include <cuda_runtime.h>
#include <cuda_bf16.h>
#include <math.h>

#define H 512
#define W 512
#define WPR 16                 // 32-bit words per row
#define GRID 128               // 4 rows per block, oe=1 (one wave, 1 block/SM)
#define NARR (GRID * 4)        // arrival count: 4 counting warps per block
#define MISS (1 << 20)

// Fixed-point weights: round(sqrt(t) * 65536)
#define K_1   65536ULL
#define K_R2  92682ULL
#define K_2   131072ULL
#define K_R5  146543ULL
#define K_2R2 185364ULL
#define K_3   196608ULL
#define K_R10 207244ULL

// Scratch (allocation-free rule: __device__ globals)
__device__ unsigned long long d_num_fp;  // fixed-point numerator (reset by last)
__device__ unsigned d_den_i;             // integer denominator (reset by last)
__device__ unsigned d_cnt;               // zero-init; atomicInc wraps -> reset

// ---------------------------------------------------------------------------
// Cold path: recompute raw/surface mask words directly from float inputs.
// Only used for pixels with nearest surface distance^2 > 10 (P ~ 3e-5 / run).
// ---------------------------------------------------------------------------
__device__ __noinline__ unsigned raw_word_f(const float* __restrict__ src,
                                            int r, int w) {
    if (r < 0 || r >= H) return 0u;
    const float* p = src + r * W + w * 32;
    unsigned x = 0;
    for (int j = 0; j < 32; ++j)
        if (p[j] != 0.0f) x |= 1u << j;
    return x;
}

__device__ __noinline__ unsigned sur_word_f(const float* __restrict__ src,
                                            int r, int w) {
    if (r < 0 || r >= H || w < 0 || w >= WPR) return 0u;
    unsigned cen = raw_word_f(src, r, w);
    unsigned up  = raw_word_f(src, r - 1, w);
    unsigned dn  = raw_word_f(src, r + 1, w);
    unsigned lb  = (w > 0)  ? ((raw_word_f(src, r, w - 1) >> 31) & 1u) : 0u;
    unsigned rb  = (w < 15) ? (raw_word_f(src, r, w + 1) & 1u) : 0u;
    unsigned lm = (cen << 1) | lb;
    unsigned rm = (cen >> 1) | (rb << 31);
    return cen & ~(up & dn & lm & rm);
}

__device__ __noinline__ float search_fb(const float* __restrict__ src,
                                        int r, int w, int bit) {
    float best = 1e12f;
    for (int dr = 0; dr < H; ++dr) {
        int dr2 = dr * dr;
        if ((float)dr2 >= best) break;
        for (int sgn = 0; sgn < 2; ++sgn) {
            if (sgn == 1 && dr == 0) continue;
            int gr = sgn ? (r + dr) : (r - dr);
            if (gr < 0 || gr >= H) continue;
            unsigned lo = sur_word_f(src, gr, w - 1);
            unsigned mi = sur_word_f(src, gr, w);
            unsigned hi = sur_word_f(src, gr, w + 1);
            unsigned long long up =
                (((unsigned long long)(mi & (0xFFFFFFFFu >> (31 - bit)))) << 32) |
                (unsigned long long)lo;
            unsigned long long dn =
                (((unsigned long long)hi) << (32 - bit)) |
                (unsigned long long)(mi >> bit);
            int dl = up ? (bit + 32) - (63 - __clzll(up)) : MISS;
            int drr = dn ? (__ffsll((long long)dn) - 1)   : MISS;
            int dc = min(dl, drr);
            if (dc <= 32) {
                best = fminf(best, (float)(dr2 + dc * dc));
            } else if ((float)(dr2 + 1024) < best) {
                int dfl = MISS, dfr = MISS;
                for (int ww = w - 2; ww >= 0; --ww) {
                    unsigned x = sur_word_f(src, gr, ww);
                    if (x) { dfl = (w - ww) * 32 + bit - (31 - __clz(x)); break; }
                }
                for (int ww = w + 2; ww < WPR; ++ww) {
                    unsigned x = sur_word_f(src, gr, ww);
                    if (x) { dfr = (ww - w) * 32 - bit + (__ffs(x) - 1); break; }
                }
                int dm = min(min(dfl, dfr), dc);
                if (dm < MISS)
                    best = fminf(best, (float)(dr2 + dm * dm));
            }
        }
    }
    return sqrtf(best);
}

// ===========================================================================
// Single kernel, 128 blocks x 512 threads. Block b handles rows 4b..4b+3.
// R16 structure (batched loads, erosion on warps 4-13, early retirement)
// with a fixed-point integer-atomic tail: no partial arrays, no last-block
// fold -- the 512th arriving warp finalizes. Integer adds commute ->
// bit-deterministic result (quantization ~2e-8 relative).
// ===========================================================================
__global__ void __launch_bounds__(512) k_all(const float* __restrict__ pred,
                                             const float* __restrict__ gt,
                                             float* __restrict__ out) {
    __shared__ unsigned sraw[2][12][WPR];   // raw rows gb-4..gb+7
    __shared__ unsigned stg[2][10][18];     // surface rows gb-3..gb+6, padded

    const int c = threadIdx.x;
    const int lane = c & 31;
    const int wwarp = c >> 5;               // warp id == word index
    const int gb = blockIdx.x * 4;

    // ---- batched loads: 3 batches x 4 rows x 2 features (MLP_p1 ~ 8) ----
    #pragma unroll
    for (int bb = 0; bb < 3; ++bb) {
        float pv[4], gv[4];
        #pragma unroll
        for (int k = 0; k < 4; ++k) {
            int rr = bb * 4 + k;
            int gr = gb - 4 + rr;
            bool ok = (gr >= 0) && (gr < H);
            pv[k] = ok ? pred[gr * W + c] : 0.0f;
            gv[k] = ok ? gt[gr * W + c]   : 0.0f;
        }
        #pragma unroll
        for (int k = 0; k < 4; ++k) {
            int rr = bb * 4 + k;
            unsigned ba = __ballot_sync(0xFFFFFFFFu, pv[k] != 0.0f);
            unsigned bg = __ballot_sync(0xFFFFFFFFu, gv[k] != 0.0f);
            if (lane == 0) { sraw[0][rr][wwarp] = ba; sraw[1][rr][wwarp] = bg; }
        }
    }
    __syncthreads();

    // ---- bitwise erosion on warps 4..13 (threads 128..447) ----
    if (c >= 128 && c < 448) {
        int t = c - 128;                      // 0..319
        int f = t / 160, rest = t % 160;
        int rr = rest >> 4, ww = rest & 15;   // rr 0..9 -> surface row gb-3+rr
        int ri = rr + 1;                      // center raw row index
        unsigned cen = sraw[f][ri][ww];
        unsigned up = sraw[f][ri - 1][ww];
        unsigned dn = sraw[f][ri + 1][ww];
        unsigned lw = (ww > 0)  ? sraw[f][ri][ww - 1] : 0u;
        unsigned rw = (ww < 15) ? sraw[f][ri][ww + 1] : 0u;
        unsigned lm = (cen << 1) | (lw >> 31);
        unsigned rm = (cen >> 1) | (rw << 31);
        stg[f][rr][ww + 1] = cen & ~(up & dn & lm & rm);
    } else if (c >= 448 && c < 488) {
        int idx = c - 448;                    // 40 pad words -> 0
        int f = idx / 20, rest = idx % 20;
        stg[f][rest >> 1][(rest & 1) ? 17 : 0] = 0u;
    }
    __syncthreads();

    // warps 4..15 retire
    if (wwarp >= 4) return;

    // ---- per-word ball-dilation counting (2 feat x 4 rows x 16 words) ----
    unsigned long long num_fp = 0ULL;
    unsigned den_i = 0u;

    {
        const int f = c >> 6;            // dilated (source) feature
        const int local = c & 63;
        const int rloc = local >> 4;     // 0..3
        const int w = local & 15;
        const int gr = gb + rloc;

        unsigned a0c0, a0c1, a0c2, a0c3;
        unsigned a1c0 = 0, a1c1 = 0, a1c2 = 0, a1c3 = 0;
        unsigned a2c0 = 0, a2c1 = 0, a2c2 = 0;
        unsigned a3c0 = 0, a3c1 = 0;

        #pragma unroll
        for (int dr = -3; dr <= 3; ++dr) {
            const unsigned* row = &stg[f][rloc + 3 + dr][0];
            unsigned lo = row[w], mi = row[w + 1], hi = row[w + 2];
            unsigned c0 = mi;
            unsigned c1 = __funnelshift_r(mi, hi, 1) | __funnelshift_l(lo, mi, 1);
            const int adr = (dr < 0) ? -dr : dr;
            if (adr == 0) {
                a0c0 = c0; a0c1 = c1;
                a0c2 = __funnelshift_r(mi, hi, 2) | __funnelshift_l(lo, mi, 2);
                a0c3 = __funnelshift_r(mi, hi, 3) | __funnelshift_l(lo, mi, 3);
            } else if (adr == 1) {
                a1c0 |= c0; a1c1 |= c1;
                a1c2 |= __funnelshift_r(mi, hi, 2) | __funnelshift_l(lo, mi, 2);
                a1c3 |= __funnelshift_r(mi, hi, 3) | __funnelshift_l(lo, mi, 3);
            } else if (adr == 2) {
                a2c0 |= c0; a2c1 |= c1;
                a2c2 |= __funnelshift_r(mi, hi, 2) | __funnelshift_l(lo, mi, 2);
            } else {
                a3c0 |= c0; a3c1 |= c1;
            }
        }

        const unsigned tgt = stg[f ^ 1][rloc + 3][w + 1];
        den_i = (unsigned)__popc(tgt);

        // incremental ball dilations: d^2 = 0,1,2,4,5,8,9,10 (fixed point)
        unsigned D = a0c0, Dn;
        Dn = D | a0c1 | a1c0; num_fp += K_1   * (unsigned long long)__popc(tgt & Dn & ~D); D = Dn;
        Dn = D | a1c1;        num_fp += K_R2  * (unsigned long long)__popc(tgt & Dn & ~D); D = Dn;
        Dn = D | a0c2 | a2c0; num_fp += K_2   * (unsigned long long)__popc(tgt & Dn & ~D); D = Dn;
        Dn = D | a1c2 | a2c1; num_fp += K_R5  * (unsigned long long)__popc(tgt & Dn & ~D); D = Dn;
        Dn = D | a2c2;        num_fp += K_2R2 * (unsigned long long)__popc(tgt & Dn & ~D); D = Dn;
        Dn = D | a0c3 | a3c0; num_fp += K_3   * (unsigned long long)__popc(tgt & Dn & ~D); D = Dn;
        Dn = D | a1c3 | a3c1; num_fp += K_R10 * (unsigned long long)__popc(tgt & Dn & ~D); D = Dn;

        // cold exact fallback -> fixed point
        unsigned rem = tgt & ~D;
        while (rem) {
            int bt = __ffs(rem) - 1;
            rem &= rem - 1u;
            float fb = search_fb(f ? gt : pred, gr, w, bt);
            num_fp += (unsigned long long)llrintf(fb * 65536.0f);
        }
    }

    // ---- per-warp integer fold + direct global atomics (order-independent) ----
    #pragma unroll
    for (int off = 16; off > 0; off >>= 1) {
        num_fp += __shfl_down_sync(0xFFFFFFFFu, num_fp, off);
        den_i  += __shfl_down_sync(0xFFFFFFFFu, den_i,  off);
    }

    if (lane == 0) {
        atomicAdd(&d_num_fp, num_fp);
        atomicAdd(&d_den_i, den_i);
        __threadfence();
        unsigned old = atomicInc(&d_cnt, NARR - 1);   // wraps -> self-reset
        if (old == NARR - 1) {
            __threadfence();
            unsigned long long nf = atomicAdd(&d_num_fp, 0ULL);
            unsigned df = atomicAdd(&d_den_i, 0u);
            out[0] = (float)(((double)nf / 65536.0) / (double)df);
            d_num_fp = 0ULL;       // reset for next graph replay
            d_den_i = 0u;
        }
    }
}

extern "C" void kernel_launch(void* const* d_in, const int* in_sizes, int n_in,
                              void* d_out, int out_size) {
    const float* pred = (const float*)d_in[0];
    const float* gt   = (const float*)d_in[1];
    float* out = (float*)d_out;

    k_all<<<GRID, 512>>>(pred, gt, out);
}